// round 14
// baseline (speedup 1.0000x reference)
#include <cuda_runtime.h>
#include <cuda_bf16.h>
#include <cstdint>

#define NCHUNK 20
#define NIT    11               // 2 xlin dense + 1 silu pair + 8 spline pairs
#define TMR    128
#define THREADS 256
#define A_HL   18432            // bytes per A image (128 rows x 144B)
#define A_BUF  (2 * A_HL)       // two slots
#define OF_A   0
#define OF_B   (2 * A_BUF)                  // 73728
#define SMEM_TOTAL (OF_B + 2 * 16384)       // 106496

// Single-bf16 B fragments (16 spline + 2 silu chunks): [c][kt][nt][lane] = uint2(b0, b1)
__device__ __align__(16) uint2 g_Bs[18 * 4 * 8 * 32];
// x_lin B fragments (hi/lo): [c-18][kt][nt][lane] = uint4(b0h, b1h, b0l, b1l)
__device__ __align__(16) uint4 g_Bd[2 * 4 * 8 * 32];

__device__ __forceinline__ uint32_t smem_u32(const void* p) {
    uint32_t a;
    asm("{ .reg .u64 t; cvta.to.shared.u64 t, %1; cvt.u32.u64 %0, t; }" : "=r"(a) : "l"(p));
    return a;
}
#define LDM_X4(r0, r1, r2, r3, addr) \
    asm volatile("ldmatrix.sync.aligned.m8n8.x4.shared.b16 {%0,%1,%2,%3}, [%4];" \
                 : "=r"(r0), "=r"(r1), "=r"(r2), "=r"(r3) : "r"(addr))
#define MMA16816(c, a0, a1, a2, a3, b0, b1) \
    asm volatile("mma.sync.aligned.m16n8k16.row.col.f32.bf16.bf16.f32 " \
                 "{%0,%1,%2,%3}, {%4,%5,%6,%7}, {%8,%9}, {%0,%1,%2,%3};" \
                 : "+f"((c)[0]), "+f"((c)[1]), "+f"((c)[2]), "+f"((c)[3]) \
                 : "r"(a0), "r"(a1), "r"(a2), "r"(a3), "r"(b0), "r"(b1))
#define CP_ASYNC16(dst, src) \
    asm volatile("cp.async.ca.shared.global [%0], [%1], 16;" :: "r"(dst), "l"(src) : "memory")
#define CP_COMMIT() asm volatile("cp.async.commit_group;" ::: "memory")
#define CP_WAIT0()  asm volatile("cp.async.wait_group 0;" ::: "memory")

__device__ __forceinline__ uint32_t pkbf2(float lo, float hi) {
    uint32_t d;
    asm("cvt.rn.bf16x2.f32 %0, %1, %2;" : "=r"(d) : "f"(hi), "f"(lo));
    return d;
}
__device__ __forceinline__ void bsplit(float v, unsigned short& h, unsigned short& l) {
    __nv_bfloat16 bh = __float2bfloat16(v);
    h = __bfloat16_as_ushort(bh);
    l = __bfloat16_as_ushort(__float2bfloat16(v - __bfloat162float(bh)));
}
__device__ __forceinline__ float wval(int c, int k, int n,
                                      const float* W1, const float* coef,
                                      const float* sb, const float* sp,
                                      const float* mask) {
    if (c < 16) {
        int i = c * 8 + (k >> 3), j = k & 7, io = i * 64 + n;
        return coef[io * 8 + j] * sp[io] * mask[io];
    }
    if (c < 18) {
        int io = ((c - 16) * 64 + k) * 64 + n;
        return sb[io] * mask[io];
    }
    return W1[n * 128 + (c - 18) * 64 + k];
}

__global__ void prepB_kernel(const float* __restrict__ W1, const float* __restrict__ coef,
                             const float* __restrict__ sb, const float* __restrict__ sp,
                             const float* __restrict__ mask) {
    int idx = blockIdx.x * blockDim.x + threadIdx.x;
    if (idx >= NCHUNK * 4 * 8 * 32) return;
    int lane = idx & 31, nt = (idx >> 5) & 7, kt = (idx >> 8) & 3, c = idx >> 10;
    int n  = nt * 8 + (lane >> 2);
    int k0 = kt * 16 + (lane & 3) * 2;
    float v00 = wval(c, k0,     n, W1, coef, sb, sp, mask);
    float v01 = wval(c, k0 + 1, n, W1, coef, sb, sp, mask);
    float v10 = wval(c, k0 + 8, n, W1, coef, sb, sp, mask);
    float v11 = wval(c, k0 + 9, n, W1, coef, sb, sp, mask);
    if (c < 18) {
        uint2 r;
        r.x = pkbf2(v00, v01);
        r.y = pkbf2(v10, v11);
        g_Bs[idx] = r;
    } else {
        unsigned short h00, l00, h01, l01, h10, l10, h11, l11;
        bsplit(v00, h00, l00); bsplit(v01, h01, l01);
        bsplit(v10, h10, l10); bsplit(v11, h11, l11);
        uint4 r;
        r.x = (unsigned)h00 | ((unsigned)h01 << 16);
        r.y = (unsigned)h10 | ((unsigned)h11 << 16);
        r.z = (unsigned)l00 | ((unsigned)l01 << 16);
        r.w = (unsigned)l10 | ((unsigned)l11 << 16);
        g_Bd[idx - 18 * 1024] = r;
    }
}

// ---- spline-pair A-prep: chunks c0, c0+1; thread = 4 contiguous feats x 1 row ----
__device__ __forceinline__ void prepSplinePair(int c0, int nb, int t, char* smA,
                                               const float* __restrict__ x,
                                               int n0, int N, float g0, float invh) {
    const int fq  = (t & 3) * 4;         // 0,4,8,12 within the 16-feat pair span
    const int sub = fq >> 3;             // 0 or 1 (which chunk of the pair)
    const int fl0 = fq & 7;              // feat-local base within sub
    char* dst = smA + nb * A_BUF + sub * A_HL;
#pragma unroll
    for (int e = 0; e < 2; ++e) {
        const int row = (t >> 2) + e * 64;
        int gn = n0 + row; if (gn >= N) gn = N - 1;
        float4 v = __ldg((const float4*)(x + (size_t)gn * 128 + c0 * 8 + fq));
        float fv[4] = {v.x, v.y, v.z, v.w};
#pragma unroll
        for (int j = 0; j < 4; ++j) {
            float a  = fv[j];
            float tt = (a - g0) * invh;
            float mf = floorf(tt);
            float u  = tt - mf;
            float w0, w1, w2, w3; int m;
            if (tt >= 0.0f && mf <= 10.0f) {
                m = (int)mf;
                float u2 = u * u, u3 = u2 * u, omu = 1.0f - u;
                w0 = (1.0f / 6.0f) * omu * omu * omu;
                w1 = (1.0f / 6.0f) * (3.0f * u3 - 6.0f * u2 + 4.0f);
                w2 = (1.0f / 6.0f) * (-3.0f * u3 + 3.0f * u2 + 3.0f * u + 1.0f);
                w3 = (1.0f / 6.0f) * u3;
            } else { m = 100; w0 = w1 = w2 = w3 = 0.f; }
            char* dH = dst + row * 144 + (fl0 + j) * 16;
            *(uint4*)dH = make_uint4(0, 0, 0, 0);
            int j0 = (m - 3) & ~1, p = (m - 3) & 1;
            float a0 = p ? 0.f : w0, b0 = p ? w0 : w1;
            float a1 = p ? w1 : w2, b1 = p ? w2 : w3;
            uint32_t W0 = pkbf2(a0, b0), W1 = pkbf2(a1, b1), W2 = pkbf2(w3, 0.f);
            if ((unsigned)j0 <= 6u)       *(uint32_t*)(dH + j0 * 2) = W0;
            if ((unsigned)(j0 + 2) <= 6u) *(uint32_t*)(dH + (j0 + 2) * 2) = W1;
            if (p && (unsigned)(j0 + 4) <= 6u) *(uint32_t*)(dH + (j0 + 4) * 2) = W2;
        }
    }
}

// ---- silu-pair A-prep: chunks 16,17 (feats 0..63 -> slot 0, 64..127 -> slot 1) ----
__device__ __forceinline__ void prepSiluPair(int nb, int t, char* smA,
                                             const float* __restrict__ x,
                                             int n0, int N) {
    const int row = t >> 1, half = t & 1;
    int gn = n0 + row; if (gn >= N) gn = N - 1;
    const float4* xp = (const float4*)(x + (size_t)gn * 128 + half * 64);
    char* dst = smA + nb * A_BUF + half * A_HL + row * 144;
#pragma unroll
    for (int pass = 0; pass < 2; ++pass) {
        float vv[32];
#pragma unroll
        for (int q = 0; q < 8; ++q) {
            float4 v = __ldg(xp + pass * 8 + q);
            vv[q * 4 + 0] = v.x; vv[q * 4 + 1] = v.y; vv[q * 4 + 2] = v.z; vv[q * 4 + 3] = v.w;
        }
        uint32_t hq[16];
#pragma unroll
        for (int q = 0; q < 16; ++q) {
            float pa = vv[2 * q], pb = vv[2 * q + 1];
            pa = pa / (1.0f + __expf(-pa));
            pb = pb / (1.0f + __expf(-pb));
            hq[q] = pkbf2(pa, pb);
        }
#pragma unroll
        for (int q = 0; q < 4; ++q)
            *(uint4*)(dst + pass * 64 + q * 16) =
                make_uint4(hq[q * 4 + 0], hq[q * 4 + 1], hq[q * 4 + 2], hq[q * 4 + 3]);
    }
}

// ---- x_lin dense A-prep: hi slot 0, lo slot 1 ----
__device__ __forceinline__ void prepDense(int cc, int nb, int t, char* smA,
                                          const float* __restrict__ x,
                                          int n0, int N) {
    char* bAh = smA + nb * A_BUF;
    char* bAl = bAh + A_HL;
    const int i0 = (cc & 1) * 64, row = t >> 1, half = t & 1;
    int gn = n0 + row; if (gn >= N) gn = N - 1;
    const float4* xp = (const float4*)(x + (size_t)gn * 128 + i0 + half * 32);
    float vv[32];
#pragma unroll
    for (int q = 0; q < 8; ++q) {
        float4 v = __ldg(xp + q);
        vv[q * 4 + 0] = v.x; vv[q * 4 + 1] = v.y; vv[q * 4 + 2] = v.z; vv[q * 4 + 3] = v.w;
    }
    uint32_t hq[16], lq[16];
#pragma unroll
    for (int q = 0; q < 16; ++q) {
        float pa = vv[2 * q], pb = vv[2 * q + 1];
        hq[q] = pkbf2(pa, pb);
        float ra = pa - __uint_as_float(hq[q] << 16);
        float rb = pb - __uint_as_float(hq[q] & 0xffff0000u);
        lq[q] = pkbf2(ra, rb);
    }
    char* dH = bAh + row * 144 + half * 64;
    char* dL = bAl + row * 144 + half * 64;
#pragma unroll
    for (int q = 0; q < 4; ++q) {
        *(uint4*)(dH + q * 16) = make_uint4(hq[q * 4 + 0], hq[q * 4 + 1], hq[q * 4 + 2], hq[q * 4 + 3]);
        *(uint4*)(dL + q * 16) = make_uint4(lq[q * 4 + 0], lq[q * 4 + 1], lq[q * 4 + 2], lq[q * 4 + 3]);
    }
}

// iteration order g = 0..10: g 0,1 = xlin chunks 18,19; g 2 = silu pair (16,17);
// g 3..10 = spline pairs 0..7.
__device__ __forceinline__ void stageB(int g, int nb, int t, uint32_t bSm) {
    uint32_t bdst = bSm + nb * 16384 + t * 16;
    const char* bsrc;
    if (g < 2)       bsrc = (const char*)(g_Bd + g * 1024) + t * 16;
    else if (g == 2) bsrc = (const char*)(g_Bs + 16 * 1024) + t * 16;
    else             bsrc = (const char*)(g_Bs + (g - 3) * 2048) + t * 16;
#pragma unroll
    for (int q = 0; q < 4; ++q) CP_ASYNC16(bdst + q * 4096, bsrc + q * 4096);
    CP_COMMIT();
}

__device__ __forceinline__ void prepIt(int g, int nb, int t, char* smA,
                                       const float* __restrict__ x,
                                       int n0, int N, float g0, float invh) {
    if (g < 2)       prepDense(18 + g, nb, t, smA, x, n0, N);
    else if (g == 2) prepSiluPair(nb, t, smA, x, n0, N);
    else             prepSplinePair((g - 3) * 2, nb, t, smA, x, n0, N, g0, invh);
}

__global__ __launch_bounds__(THREADS, 2)
void enc_mma_kernel(const float* __restrict__ x, const float* __restrict__ gridp,
                    float* __restrict__ zout, float* __restrict__ xlout, int N) {
    extern __shared__ char sm[];
    char* smA = sm + OF_A;

    const int t = threadIdx.x, wid = t >> 5, lane = t & 31;
    const int wr = wid & 3, wc = wid >> 2;     // warp: rows wr*32..+31, cols wc*32..+31
    const int n0 = blockIdx.x * TMR;

    const float g0   = gridp[0];
    const float invh = 1.0f / (gridp[1] - gridp[0]);

    float accz[2][4][4];
#pragma unroll
    for (int rt = 0; rt < 2; rt++)
#pragma unroll
        for (int nt = 0; nt < 4; nt++)
#pragma unroll
            for (int q = 0; q < 4; q++) accz[rt][nt][q] = 0.f;

    const int lrow = wr * 32 + (lane & 7) + ((lane >> 3) & 1) * 8;
    const uint32_t aOff = smem_u32(smA) + lrow * 144 + ((lane >> 4) * 8) * 2;
    const uint32_t bSm  = smem_u32(sm + OF_B);

    // ---------------- prologue ----------------
    stageB(0, 0, t, bSm);
    prepIt(0, 0, t, smA, x, n0, N, g0, invh);
    CP_WAIT0();
    __syncthreads();

    // ---------------- peeled x_lin iterations (g = 0, 1) ----------------
    {
        float accx[2][4][4];
#pragma unroll
        for (int rt = 0; rt < 2; rt++)
#pragma unroll
            for (int nt = 0; nt < 4; nt++)
#pragma unroll
                for (int q = 0; q < 4; q++) accx[rt][nt][q] = 0.f;

#pragma unroll
        for (int g = 0; g < 2; ++g) {
            const int cb = g & 1, nb = cb ^ 1;
            stageB(g + 1, nb, t, bSm);
            const uint4* sBb = (const uint4*)(sm + OF_B + cb * 16384);
            const uint32_t aH = aOff + cb * A_BUF;
#pragma unroll
            for (int kt = 0; kt < 4; ++kt) {
                uint4 B[4];
#pragma unroll
                for (int nt = 0; nt < 4; ++nt) B[nt] = sBb[(kt * 8 + wc * 4 + nt) * 32 + lane];
#pragma unroll
                for (int rt = 0; rt < 2; ++rt) {
                    uint32_t ah0, ah1, ah2, ah3, al0, al1, al2, al3;
                    LDM_X4(ah0, ah1, ah2, ah3, aH + rt * (16 * 144) + kt * 32);
                    LDM_X4(al0, al1, al2, al3, aH + A_HL + rt * (16 * 144) + kt * 32);
#pragma unroll
                    for (int nt = 0; nt < 4; ++nt) {
                        MMA16816(accx[rt][nt], ah0, ah1, ah2, ah3, B[nt].x, B[nt].y);
                        MMA16816(accx[rt][nt], ah0, ah1, ah2, ah3, B[nt].z, B[nt].w);
                        MMA16816(accx[rt][nt], al0, al1, al2, al3, B[nt].x, B[nt].y);
                    }
                }
            }
            prepIt(g + 1, nb, t, smA, x, n0, N, g0, invh);
            CP_WAIT0();
            __syncthreads();
        }

        // store x_lin now; accx dies here
#pragma unroll
        for (int rt = 0; rt < 2; ++rt) {
            const int r0 = wr * 32 + rt * 16 + (lane >> 2), r1 = r0 + 8;
            const bool ok0 = (n0 + r0 < N), ok1 = (n0 + r1 < N);
#pragma unroll
            for (int nt = 0; nt < 4; ++nt) {
                int n = wc * 32 + nt * 8 + (lane & 3) * 2;
                if (ok0) *(float2*)(xlout + (size_t)(n0 + r0) * 64 + n) =
                             make_float2(accx[rt][nt][0], accx[rt][nt][1]);
                if (ok1) *(float2*)(xlout + (size_t)(n0 + r1) * 64 + n) =
                             make_float2(accx[rt][nt][2], accx[rt][nt][3]);
            }
        }
    }

    // ---------------- steady-state pair iterations (g = 2..10) ----------------
#pragma unroll 1
    for (int g = 2; g < NIT; ++g) {
        const int cb = g & 1, nb = cb ^ 1;
        const bool more = (g + 1 < NIT);
        if (more) stageB(g + 1, nb, t, bSm);
#pragma unroll
        for (int h = 0; h < 2; ++h) {
            const uint2* sB2 = (const uint2*)(sm + OF_B + cb * 16384 + h * 8192);
            const uint32_t aH = aOff + cb * A_BUF + h * A_HL;
#pragma unroll
            for (int kt = 0; kt < 4; ++kt) {
                uint2 B[4];
#pragma unroll
                for (int nt = 0; nt < 4; ++nt) B[nt] = sB2[(kt * 8 + wc * 4 + nt) * 32 + lane];
#pragma unroll
                for (int rt = 0; rt < 2; ++rt) {
                    uint32_t ah0, ah1, ah2, ah3;
                    LDM_X4(ah0, ah1, ah2, ah3, aH + rt * (16 * 144) + kt * 32);
#pragma unroll
                    for (int nt = 0; nt < 4; ++nt)
                        MMA16816(accz[rt][nt], ah0, ah1, ah2, ah3, B[nt].x, B[nt].y);
                }
            }
        }
        if (more) prepIt(g + 1, nb, t, smA, x, n0, N, g0, invh);
        CP_WAIT0();
        __syncthreads();
    }

    // ---------------- epilogue: z row-norm + store ----------------
    float* spart = (float*)sm;   // reuse A region: [coltile][row] 2x128
#pragma unroll
    for (int rt = 0; rt < 2; ++rt) {
        float p0 = 0.f, p1 = 0.f;
#pragma unroll
        for (int nt = 0; nt < 4; ++nt) {
            p0 += accz[rt][nt][0] * accz[rt][nt][0] + accz[rt][nt][1] * accz[rt][nt][1];
            p1 += accz[rt][nt][2] * accz[rt][nt][2] + accz[rt][nt][3] * accz[rt][nt][3];
        }
        p0 += __shfl_xor_sync(0xffffffffu, p0, 1);
        p0 += __shfl_xor_sync(0xffffffffu, p0, 2);
        p1 += __shfl_xor_sync(0xffffffffu, p1, 1);
        p1 += __shfl_xor_sync(0xffffffffu, p1, 2);
        if ((lane & 3) == 0) {
            int r0 = wr * 32 + rt * 16 + (lane >> 2);
            spart[wc * TMR + r0]     = p0;
            spart[wc * TMR + r0 + 8] = p1;
        }
    }
    __syncthreads();

#pragma unroll
    for (int rt = 0; rt < 2; ++rt) {
        const int r0 = wr * 32 + rt * 16 + (lane >> 2), r1 = r0 + 8;
        const float fac0 = 0.8f / fmaxf(sqrtf(spart[r0] + spart[TMR + r0]), 1e-12f);
        const float fac1 = 0.8f / fmaxf(sqrtf(spart[r1] + spart[TMR + r1]), 1e-12f);
        const bool ok0 = (n0 + r0 < N), ok1 = (n0 + r1 < N);
#pragma unroll
        for (int nt = 0; nt < 4; ++nt) {
            int n = wc * 32 + nt * 8 + (lane & 3) * 2;
            if (ok0) *(float2*)(zout + (size_t)(n0 + r0) * 64 + n) =
                         make_float2(accz[rt][nt][0] * fac0, accz[rt][nt][1] * fac0);
            if (ok1) *(float2*)(zout + (size_t)(n0 + r1) * 64 + n) =
                         make_float2(accz[rt][nt][2] * fac1, accz[rt][nt][3] * fac1);
        }
    }
}

extern "C" void kernel_launch(void* const* d_in, const int* in_sizes, int n_in,
                              void* d_out, int out_size) {
    const float* x          = (const float*)d_in[0];
    const float* W1         = (const float*)d_in[1];
    const float* grid       = (const float*)d_in[2];
    const float* coef       = (const float*)d_in[3];
    const float* scale_base = (const float*)d_in[4];
    const float* scale_sp   = (const float*)d_in[5];
    const float* mask       = (const float*)d_in[6];
    // d_in[7] = edge_index: unused by the reference

    const int N = in_sizes[0] / 128;
    float* out   = (float*)d_out;
    float* zout  = out;
    float* xlout = out + (size_t)N * 64;

    cudaFuncSetAttribute(enc_mma_kernel, cudaFuncAttributeMaxDynamicSharedMemorySize, SMEM_TOTAL);
    prepB_kernel<<<(NCHUNK * 4 * 8 * 32 + 255) / 256, 256>>>(W1, coef, scale_base, scale_sp, mask);
    enc_mma_kernel<<<(N + TMR - 1) / TMR, THREADS, SMEM_TOTAL>>>(x, grid, zout, xlout, N);
}

// round 16
// speedup vs baseline: 1.0315x; 1.0315x over previous
#include <cuda_runtime.h>
#include <cuda_bf16.h>
#include <cstdint>

#define NCHUNK 20
#define NIT    11               // 8 spline pairs + 1 silu pair + 2 xlin dense
#define TMR    128
#define THREADS 256
#define A_HL   18432            // bytes per A image (128 rows x 144B)
#define A_BUF  (2 * A_HL)       // two slots
#define OF_A   0
#define OF_B   (2 * A_BUF)                  // 73728
#define SMEM_TOTAL (OF_B + 2 * 16384)       // 106496

// Single-bf16 B fragments (16 spline + 2 silu chunks): [c][kt][nt][lane] = uint2(b0, b1)
__device__ __align__(16) uint2 g_Bs[18 * 4 * 8 * 32];
// x_lin B fragments (hi/lo): [c-18][kt][nt][lane] = uint4(b0h, b1h, b0l, b1l)
__device__ __align__(16) uint4 g_Bd[2 * 4 * 8 * 32];

__device__ __forceinline__ uint32_t smem_u32(const void* p) {
    uint32_t a;
    asm("{ .reg .u64 t; cvta.to.shared.u64 t, %1; cvt.u32.u64 %0, t; }" : "=r"(a) : "l"(p));
    return a;
}
#define LDM_X4(r0, r1, r2, r3, addr) \
    asm volatile("ldmatrix.sync.aligned.m8n8.x4.shared.b16 {%0,%1,%2,%3}, [%4];" \
                 : "=r"(r0), "=r"(r1), "=r"(r2), "=r"(r3) : "r"(addr))
#define MMA16816(c, a0, a1, a2, a3, b0, b1) \
    asm volatile("mma.sync.aligned.m16n8k16.row.col.f32.bf16.bf16.f32 " \
                 "{%0,%1,%2,%3}, {%4,%5,%6,%7}, {%8,%9}, {%0,%1,%2,%3};" \
                 : "+f"((c)[0]), "+f"((c)[1]), "+f"((c)[2]), "+f"((c)[3]) \
                 : "r"(a0), "r"(a1), "r"(a2), "r"(a3), "r"(b0), "r"(b1))
#define CP_ASYNC16(dst, src) \
    asm volatile("cp.async.cg.shared.global [%0], [%1], 16;" :: "r"(dst), "l"(src) : "memory")
#define CP_COMMIT() asm volatile("cp.async.commit_group;" ::: "memory")
#define CP_WAIT0()  asm volatile("cp.async.wait_group 0;" ::: "memory")

__device__ __forceinline__ uint32_t pkbf2(float lo, float hi) {
    uint32_t d;
    asm("cvt.rn.bf16x2.f32 %0, %1, %2;" : "=r"(d) : "f"(hi), "f"(lo));
    return d;
}
__device__ __forceinline__ void bsplit(float v, unsigned short& h, unsigned short& l) {
    __nv_bfloat16 bh = __float2bfloat16(v);
    h = __bfloat16_as_ushort(bh);
    l = __bfloat16_as_ushort(__float2bfloat16(v - __bfloat162float(bh)));
}
__device__ __forceinline__ float wval(int c, int k, int n,
                                      const float* W1, const float* coef,
                                      const float* sb, const float* sp,
                                      const float* mask) {
    if (c < 16) {
        int i = c * 8 + (k >> 3), j = k & 7, io = i * 64 + n;
        return coef[io * 8 + j] * sp[io] * mask[io];
    }
    if (c < 18) {
        int io = ((c - 16) * 64 + k) * 64 + n;
        return sb[io] * mask[io];
    }
    return W1[n * 128 + (c - 18) * 64 + k];
}

__global__ void prepB_kernel(const float* __restrict__ W1, const float* __restrict__ coef,
                             const float* __restrict__ sb, const float* __restrict__ sp,
                             const float* __restrict__ mask) {
    int idx = blockIdx.x * blockDim.x + threadIdx.x;
    if (idx >= NCHUNK * 4 * 8 * 32) return;
    int lane = idx & 31, nt = (idx >> 5) & 7, kt = (idx >> 8) & 3, c = idx >> 10;
    int n  = nt * 8 + (lane >> 2);
    int k0 = kt * 16 + (lane & 3) * 2;
    float v00 = wval(c, k0,     n, W1, coef, sb, sp, mask);
    float v01 = wval(c, k0 + 1, n, W1, coef, sb, sp, mask);
    float v10 = wval(c, k0 + 8, n, W1, coef, sb, sp, mask);
    float v11 = wval(c, k0 + 9, n, W1, coef, sb, sp, mask);
    if (c < 18) {
        uint2 r;
        r.x = pkbf2(v00, v01);
        r.y = pkbf2(v10, v11);
        g_Bs[idx] = r;
    } else {
        unsigned short h00, l00, h01, l01, h10, l10, h11, l11;
        bsplit(v00, h00, l00); bsplit(v01, h01, l01);
        bsplit(v10, h10, l10); bsplit(v11, h11, l11);
        uint4 r;
        r.x = (unsigned)h00 | ((unsigned)h01 << 16);
        r.y = (unsigned)h10 | ((unsigned)h11 << 16);
        r.z = (unsigned)l00 | ((unsigned)l01 << 16);
        r.w = (unsigned)l10 | ((unsigned)l11 << 16);
        g_Bd[idx - 18 * 1024] = r;
    }
}

// ---- spline-pair A-prep (R14 float4 version, correctness-verified):
// thread = 4 contiguous feats x 1 row; 2 LDG.128 per thread ----
__device__ __forceinline__ void prepSplinePair(int c0, int nb, int t, char* smA,
                                               const float* __restrict__ x,
                                               int n0, int N, float g0, float invh) {
    const int fq  = (t & 3) * 4;         // 0,4,8,12 within the 16-feat pair span
    const int sub = fq >> 3;             // 0 or 1 (which chunk of the pair)
    const int fl0 = fq & 7;              // feat-local base within sub
    char* dst = smA + nb * A_BUF + sub * A_HL;
#pragma unroll
    for (int e = 0; e < 2; ++e) {
        const int row = (t >> 2) + e * 64;
        int gn = n0 + row; if (gn >= N) gn = N - 1;
        float4 v = __ldg((const float4*)(x + (size_t)gn * 128 + c0 * 8 + fq));
        float fv[4] = {v.x, v.y, v.z, v.w};
#pragma unroll
        for (int j = 0; j < 4; ++j) {
            float a  = fv[j];
            float tt = (a - g0) * invh;
            float mf = floorf(tt);
            float u  = tt - mf;
            float w0, w1, w2, w3; int m;
            if (tt >= 0.0f && mf <= 10.0f) {
                m = (int)mf;
                float u2 = u * u, u3 = u2 * u, omu = 1.0f - u;
                w0 = (1.0f / 6.0f) * omu * omu * omu;
                w1 = (1.0f / 6.0f) * (3.0f * u3 - 6.0f * u2 + 4.0f);
                w2 = (1.0f / 6.0f) * (-3.0f * u3 + 3.0f * u2 + 3.0f * u + 1.0f);
                w3 = (1.0f / 6.0f) * u3;
            } else { m = 100; w0 = w1 = w2 = w3 = 0.f; }
            char* dH = dst + row * 144 + (fl0 + j) * 16;
            *(uint4*)dH = make_uint4(0, 0, 0, 0);
            int j0 = (m - 3) & ~1, p = (m - 3) & 1;
            float a0 = p ? 0.f : w0, b0 = p ? w0 : w1;
            float a1 = p ? w1 : w2, b1 = p ? w2 : w3;
            uint32_t W0 = pkbf2(a0, b0), W1 = pkbf2(a1, b1), W2 = pkbf2(w3, 0.f);
            if ((unsigned)j0 <= 6u)       *(uint32_t*)(dH + j0 * 2) = W0;
            if ((unsigned)(j0 + 2) <= 6u) *(uint32_t*)(dH + (j0 + 2) * 2) = W1;
            if (p && (unsigned)(j0 + 4) <= 6u) *(uint32_t*)(dH + (j0 + 4) * 2) = W2;
        }
    }
}

// ---- silu-pair A-prep: chunks 16,17 (feats 0..63 -> slot 0, 64..127 -> slot 1) ----
__device__ __forceinline__ void prepSiluPair(int nb, int t, char* smA,
                                             const float* __restrict__ x,
                                             int n0, int N) {
    const int row = t >> 1, half = t & 1;
    int gn = n0 + row; if (gn >= N) gn = N - 1;
    const float4* xp = (const float4*)(x + (size_t)gn * 128 + half * 64);
    char* dst = smA + nb * A_BUF + half * A_HL + row * 144;
#pragma unroll
    for (int pass = 0; pass < 2; ++pass) {
        float vv[32];
#pragma unroll
        for (int q = 0; q < 8; ++q) {
            float4 v = __ldg(xp + pass * 8 + q);
            vv[q * 4 + 0] = v.x; vv[q * 4 + 1] = v.y; vv[q * 4 + 2] = v.z; vv[q * 4 + 3] = v.w;
        }
        uint32_t hq[16];
#pragma unroll
        for (int q = 0; q < 16; ++q) {
            float pa = vv[2 * q], pb = vv[2 * q + 1];
            pa = pa / (1.0f + __expf(-pa));
            pb = pb / (1.0f + __expf(-pb));
            hq[q] = pkbf2(pa, pb);
        }
#pragma unroll
        for (int q = 0; q < 4; ++q)
            *(uint4*)(dst + pass * 64 + q * 16) =
                make_uint4(hq[q * 4 + 0], hq[q * 4 + 1], hq[q * 4 + 2], hq[q * 4 + 3]);
    }
}

// ---- x_lin dense A-prep: hi slot 0, lo slot 1 ----
__device__ __forceinline__ void prepDense(int cc, int nb, int t, char* smA,
                                          const float* __restrict__ x,
                                          int n0, int N) {
    char* bAh = smA + nb * A_BUF;
    char* bAl = bAh + A_HL;
    const int i0 = (cc & 1) * 64, row = t >> 1, half = t & 1;
    int gn = n0 + row; if (gn >= N) gn = N - 1;
    const float4* xp = (const float4*)(x + (size_t)gn * 128 + i0 + half * 32);
    float vv[32];
#pragma unroll
    for (int q = 0; q < 8; ++q) {
        float4 v = __ldg(xp + q);
        vv[q * 4 + 0] = v.x; vv[q * 4 + 1] = v.y; vv[q * 4 + 2] = v.z; vv[q * 4 + 3] = v.w;
    }
    uint32_t hq[16], lq[16];
#pragma unroll
    for (int q = 0; q < 16; ++q) {
        float pa = vv[2 * q], pb = vv[2 * q + 1];
        hq[q] = pkbf2(pa, pb);
        float ra = pa - __uint_as_float(hq[q] << 16);
        float rb = pb - __uint_as_float(hq[q] & 0xffff0000u);
        lq[q] = pkbf2(ra, rb);
    }
    char* dH = bAh + row * 144 + half * 64;
    char* dL = bAl + row * 144 + half * 64;
#pragma unroll
    for (int q = 0; q < 4; ++q) {
        *(uint4*)(dH + q * 16) = make_uint4(hq[q * 4 + 0], hq[q * 4 + 1], hq[q * 4 + 2], hq[q * 4 + 3]);
        *(uint4*)(dL + q * 16) = make_uint4(lq[q * 4 + 0], lq[q * 4 + 1], lq[q * 4 + 2], lq[q * 4 + 3]);
    }
}

// ---- stage B for iteration 'it' into buffer nb (16KB) ----
__device__ __forceinline__ void stageB(int it, int nb, int t, uint32_t bSm) {
    uint32_t bdst = bSm + nb * 16384 + t * 16;
    const char* bsrc = (it <= 8)
        ? (const char*)(g_Bs + it * 2048) + t * 16        // pair: chunks 2it, 2it+1
        : (const char*)(g_Bd + (it - 9) * 1024) + t * 16; // xlin chunk 18 + (it-9)
#pragma unroll
    for (int q = 0; q < 4; ++q) CP_ASYNC16(bdst + q * 4096, bsrc + q * 4096);
    CP_COMMIT();
}

__device__ __forceinline__ void prepIt(int it, int nb, int t, char* smA,
                                       const float* __restrict__ x,
                                       int n0, int N, float g0, float invh) {
    if (it < 8)       prepSplinePair(it * 2, nb, t, smA, x, n0, N, g0, invh);
    else if (it == 8) prepSiluPair(nb, t, smA, x, n0, N);
    else              prepDense(it + 9, nb, t, smA, x, n0, N);
}

__global__ __launch_bounds__(THREADS, 2)
void enc_mma_kernel(const float* __restrict__ x, const float* __restrict__ gridp,
                    float* __restrict__ zout, float* __restrict__ xlout, int N) {
    extern __shared__ char sm[];
    char* smA = sm + OF_A;

    const int t = threadIdx.x, wid = t >> 5, lane = t & 31;
    const int wr = wid & 3, wc = wid >> 2;     // warp: rows wr*32..+31, cols wc*32..+31
    const int n0 = blockIdx.x * TMR;

    const float g0   = gridp[0];
    const float invh = 1.0f / (gridp[1] - gridp[0]);

    float accz[2][4][4], accx[2][4][4];
#pragma unroll
    for (int rt = 0; rt < 2; rt++)
#pragma unroll
        for (int nt = 0; nt < 4; nt++)
#pragma unroll
            for (int q = 0; q < 4; q++) { accz[rt][nt][q] = 0.f; accx[rt][nt][q] = 0.f; }

    const int lrow = wr * 32 + (lane & 7) + ((lane >> 3) & 1) * 8;
    const uint32_t aOff = smem_u32(smA) + lrow * 144 + ((lane >> 4) * 8) * 2;
    const uint32_t bSm  = smem_u32(sm + OF_B);

    // prologue
    stageB(0, 0, t, bSm);
    prepIt(0, 0, t, smA, x, n0, N, g0, invh);
    CP_WAIT0();
    __syncthreads();

    for (int it = 0; it < NIT; ++it) {
        const int cb = it & 1, nb = cb ^ 1;
        const bool more = (it + 1 < NIT);
        if (more) stageB(it + 1, nb, t, bSm);

        if (it <= 8) {
            // pair iteration (spline or silu): two single-bf16 sub-chunks, slots 0/1
#pragma unroll
            for (int h = 0; h < 2; ++h) {
                const uint2* sB2 = (const uint2*)(sm + OF_B + cb * 16384 + h * 8192);
                const uint32_t aH = aOff + cb * A_BUF + h * A_HL;
#pragma unroll
                for (int kt = 0; kt < 4; ++kt) {
                    uint2 B[4];
#pragma unroll
                    for (int nt = 0; nt < 4; ++nt) B[nt] = sB2[(kt * 8 + wc * 4 + nt) * 32 + lane];
#pragma unroll
                    for (int rt = 0; rt < 2; ++rt) {
                        uint32_t ah0, ah1, ah2, ah3;
                        LDM_X4(ah0, ah1, ah2, ah3, aH + rt * (16 * 144) + kt * 32);
#pragma unroll
                        for (int nt = 0; nt < 4; ++nt)
                            MMA16816(accz[rt][nt], ah0, ah1, ah2, ah3, B[nt].x, B[nt].y);
                    }
                }
            }
        } else {
            // x_lin dense: hi/lo 3-MMA
            const uint4* sBb = (const uint4*)(sm + OF_B + cb * 16384);
            const uint32_t aH = aOff + cb * A_BUF;
#pragma unroll
            for (int kt = 0; kt < 4; ++kt) {
                uint4 B[4];
#pragma unroll
                for (int nt = 0; nt < 4; ++nt) B[nt] = sBb[(kt * 8 + wc * 4 + nt) * 32 + lane];
#pragma unroll
                for (int rt = 0; rt < 2; ++rt) {
                    uint32_t ah0, ah1, ah2, ah3, al0, al1, al2, al3;
                    LDM_X4(ah0, ah1, ah2, ah3, aH + rt * (16 * 144) + kt * 32);
                    LDM_X4(al0, al1, al2, al3, aH + A_HL + rt * (16 * 144) + kt * 32);
#pragma unroll
                    for (int nt = 0; nt < 4; ++nt) {
                        MMA16816(accx[rt][nt], ah0, ah1, ah2, ah3, B[nt].x, B[nt].y);
                        MMA16816(accx[rt][nt], ah0, ah1, ah2, ah3, B[nt].z, B[nt].w);
                        MMA16816(accx[rt][nt], al0, al1, al2, al3, B[nt].x, B[nt].y);
                    }
                }
            }
        }
        if (more) prepIt(it + 1, nb, t, smA, x, n0, N, g0, invh);
        CP_WAIT0();
        __syncthreads();
    }

    // ---- epilogue ----
    float* spart = (float*)sm;   // reuse A region: [coltile][row] 2x128
#pragma unroll
    for (int rt = 0; rt < 2; ++rt) {
        float p0 = 0.f, p1 = 0.f;
#pragma unroll
        for (int nt = 0; nt < 4; ++nt) {
            p0 += accz[rt][nt][0] * accz[rt][nt][0] + accz[rt][nt][1] * accz[rt][nt][1];
            p1 += accz[rt][nt][2] * accz[rt][nt][2] + accz[rt][nt][3] * accz[rt][nt][3];
        }
        p0 += __shfl_xor_sync(0xffffffffu, p0, 1);
        p0 += __shfl_xor_sync(0xffffffffu, p0, 2);
        p1 += __shfl_xor_sync(0xffffffffu, p1, 1);
        p1 += __shfl_xor_sync(0xffffffffu, p1, 2);
        if ((lane & 3) == 0) {
            int r0 = wr * 32 + rt * 16 + (lane >> 2);
            spart[wc * TMR + r0]     = p0;
            spart[wc * TMR + r0 + 8] = p1;
        }
    }
    __syncthreads();

#pragma unroll
    for (int rt = 0; rt < 2; ++rt) {
        const int r0 = wr * 32 + rt * 16 + (lane >> 2), r1 = r0 + 8;
        const float fac0 = 0.8f / fmaxf(sqrtf(spart[r0] + spart[TMR + r0]), 1e-12f);
        const float fac1 = 0.8f / fmaxf(sqrtf(spart[r1] + spart[TMR + r1]), 1e-12f);
        const bool ok0 = (n0 + r0 < N), ok1 = (n0 + r1 < N);
#pragma unroll
        for (int nt = 0; nt < 4; ++nt) {
            int n = wc * 32 + nt * 8 + (lane & 3) * 2;
            if (ok0) {
                *(float2*)(zout  + (size_t)(n0 + r0) * 64 + n) = make_float2(accz[rt][nt][0] * fac0, accz[rt][nt][1] * fac0);
                *(float2*)(xlout + (size_t)(n0 + r0) * 64 + n) = make_float2(accx[rt][nt][0], accx[rt][nt][1]);
            }
            if (ok1) {
                *(float2*)(zout  + (size_t)(n0 + r1) * 64 + n) = make_float2(accz[rt][nt][2] * fac1, accz[rt][nt][3] * fac1);
                *(float2*)(xlout + (size_t)(n0 + r1) * 64 + n) = make_float2(accx[rt][nt][2], accx[rt][nt][3]);
            }
        }
    }
}

extern "C" void kernel_launch(void* const* d_in, const int* in_sizes, int n_in,
                              void* d_out, int out_size) {
    const float* x          = (const float*)d_in[0];
    const float* W1         = (const float*)d_in[1];
    const float* grid       = (const float*)d_in[2];
    const float* coef       = (const float*)d_in[3];
    const float* scale_base = (const float*)d_in[4];
    const float* scale_sp   = (const float*)d_in[5];
    const float* mask       = (const float*)d_in[6];
    // d_in[7] = edge_index: unused by the reference

    const int N = in_sizes[0] / 128;
    float* out   = (float*)d_out;
    float* zout  = out;
    float* xlout = out + (size_t)N * 64;

    cudaFuncSetAttribute(enc_mma_kernel, cudaFuncAttributeMaxDynamicSharedMemorySize, SMEM_TOTAL);
    prepB_kernel<<<(NCHUNK * 4 * 8 * 32 + 255) / 256, 256>>>(W1, coef, scale_base, scale_sp, mask);
    enc_mma_kernel<<<(N + TMR - 1) / TMR, THREADS, SMEM_TOTAL>>>(x, grid, zout, xlout, N);
}